// round 10
// baseline (speedup 1.0000x reference)
#include <cuda_runtime.h>
#include <cuda_fp16.h>
#include <math.h>
#include <cstdint>

// ---------------------------------------------------------------------------
// Problem constants
// ---------------------------------------------------------------------------
#define BATCH   4
#define TSEQ    2048
#define CEMB    1024
#define NHEAD   16
#define HDIM    64
#define C3      (3*CEMB)      // 3072
#define CFF     (4*CEMB)      // 4096
#define NROWS   (BATCH*TSEQ)  // 8192
#define LN_EPS  1e-5f

// ---------------------------------------------------------------------------
// Scratch (__device__ globals; alloc-free rule)
// ---------------------------------------------------------------------------
__device__ float  g_qkv[(size_t)NROWS * C3];     // fp32 (attention input)
__device__ float  g_att[(size_t)NROWS * CEMB];
__device__ float  g_xn [(size_t)NROWS * CEMB];
__device__ float  g_mlp[(size_t)NROWS * CEMB];
__device__ __half g_xh [(size_t)NROWS * CEMB];   // x in half
__device__ __half g_xnh[(size_t)NROWS * CEMB];   // xn in half
__device__ __half g_hh [(size_t)NROWS * CFF];    // gelu(fc1) in half
__device__ __half g_wTq[(size_t)C3  * CEMB];     // [3072,1024] half (K-major)
__device__ __half g_wT1[(size_t)CFF * CEMB];
__device__ __half g_wT2[(size_t)CEMB * CFF];

// ---------------------------------------------------------------------------
// Helpers
// ---------------------------------------------------------------------------
__device__ __forceinline__ uint32_t smem_u32(const void* p) {
    uint32_t a;
    asm("{ .reg .u64 t; cvta.to.shared.u64 t, %1; cvt.u32.u64 %0, t; }"
        : "=r"(a) : "l"(p));
    return a;
}

// SW128 swizzle on byte offsets (rows are 128 bytes)
#define SWZ(o) ((o) ^ (((o) >> 3) & 0x70))

__device__ __forceinline__ void cpasync16(uint32_t s, const void* g) {
    asm volatile("cp.async.cg.shared.global [%0], [%1], 16;" :: "r"(s), "l"(g));
}
__device__ __forceinline__ void cpasync_commit() {
    asm volatile("cp.async.commit_group;" ::: "memory");
}
template<int N>
__device__ __forceinline__ void cpasync_wait() {
    asm volatile("cp.async.wait_group %0;" :: "n"(N) : "memory");
}

// ---------------------------------------------------------------------------
// HFMA2 GEMM: C[M,N] = A[M,K]@Bt[N,K]^T + bias (opt GeLU). A,Bt half, C OutT.
// Direct __hfma2 inner loop, pairs packed over K (K-major smem => contiguous).
// fp16 partials promoted to fp32 every 16 k (sub-chains of 8 adds per lane).
// CTA tile 128x128, BK=64 halfs (128B rows, SW128), 512 threads,
// thread tile 8 rows x 4 cols. cp.async 3-stage pipeline (96KB smem).
// ---------------------------------------------------------------------------
#define BK 64
#define TILE_BYTES 16384       // 128 rows x 128 bytes
#define STAGE_BYTES 32768      // A tile + B tile
#define NSTAGE 3
#define GT_SMEM (NSTAGE * STAGE_BYTES)   // 98304

template<bool GELU, typename OutT>
__global__ __launch_bounds__(512, 1)
void h2gemm_kernel(const __half* __restrict__ A, const __half* __restrict__ Bt,
                   const float* __restrict__ bias, OutT* __restrict__ C,
                   int M, int N, int K)
{
    extern __shared__ char sm[];
    const uint32_t sbase = smem_u32(sm);

    const int t    = threadIdx.x;
    const int wid  = t >> 5;       // 16 warps -> row group (8 rows each)
    const int lane = t & 31;       // col base (cols lane + 32j)
    const int row0 = blockIdx.y * 128;
    const int col0 = blockIdx.x * 128;
    const int KT   = K / BK;

    // staging coords: 1024 16B-chunks per operand per stage, 2 per thread
    const int sr0 = t >> 3;            // rows 0..63
    const int sr1 = sr0 + 64;          // rows 64..127
    const int sch = t & 7;
    const uint32_t so0 = SWZ((uint32_t)(sr0 * 128 + sch * 16));
    const uint32_t so1 = SWZ((uint32_t)(sr1 * 128 + sch * 16));

    #define ISSUE(kt, st)                                                      \
        {                                                                      \
            const int kk_ = (kt) * BK;                                         \
            const uint32_t ab = sbase + (uint32_t)(st) * STAGE_BYTES;          \
            const uint32_t bb = ab + TILE_BYTES;                               \
            cpasync16(ab + so0, A  + (size_t)(row0 + sr0) * K + kk_ + sch*8);  \
            cpasync16(ab + so1, A  + (size_t)(row0 + sr1) * K + kk_ + sch*8);  \
            cpasync16(bb + so0, Bt + (size_t)(col0 + sr0) * K + kk_ + sch*8);  \
            cpasync16(bb + so1, Bt + (size_t)(col0 + sr1) * K + kk_ + sch*8);  \
        }

    float d[8][4];
    __half2 acc[8][4];
    #pragma unroll
    for (int i = 0; i < 8; i++)
        #pragma unroll
        for (int j = 0; j < 4; j++) {
            d[i][j] = 0.f;
            acc[i][j] = __half2half2(__ushort_as_half(0));
        }

    // prologue: stages 0,1
    ISSUE(0, 0); cpasync_commit();
    ISSUE(1, 1); cpasync_commit();

    const int m0 = wid * 8;

    int st = 0;
    for (int kt = 0; kt < KT; kt++) {
        cpasync_wait<1>();
        __syncthreads();

        const char* sa = sm + (size_t)st * STAGE_BYTES;
        const char* sb = sa + TILE_BYTES;

        #pragma unroll
        for (int kb = 0; kb < 8; kb++) {        // 8 halfs (4 k-pairs) per kb
            const uint32_t kbyte = (uint32_t)(kb * 16);
            // B: 4 conflict-free LDS.128 (cols lane+32j; distinct banks/phase)
            uint4 b4[4];
            #pragma unroll
            for (int j = 0; j < 4; j++) {
                const int n = lane + 32 * j;
                b4[j] = *(const uint4*)(sb + n * 128 + (kbyte ^ ((uint32_t)(n & 7) << 4)));
            }
            // A: 8 rows, warp-uniform addresses (broadcast)
            #pragma unroll
            for (int i = 0; i < 8; i++) {
                const uint4 a4 = *(const uint4*)(sa + (m0 + i) * 128 +
                                                 (kbyte ^ ((uint32_t)(i & 7) << 4)));
                const __half2* ah = (const __half2*)&a4;
                #pragma unroll
                for (int kp = 0; kp < 4; kp++) {
                    const __half2 av = ah[kp];
                    #pragma unroll
                    for (int j = 0; j < 4; j++)
                        acc[i][j] = __hfma2(av, ((const __half2*)&b4[j])[kp], acc[i][j]);
                }
            }
            // promote fp16 partials to fp32 every 16 k (kb odd)
            if (kb & 1) {
                #pragma unroll
                for (int i = 0; i < 8; i++)
                    #pragma unroll
                    for (int j = 0; j < 4; j++) {
                        const float2 f = __half22float2(acc[i][j]);
                        d[i][j] += f.x + f.y;
                        acc[i][j] = __half2half2(__ushort_as_half(0));
                    }
            }
        }

        const int nst = (st + 2 >= NSTAGE) ? st + 2 - NSTAGE : st + 2;
        if (kt + 2 < KT) ISSUE(kt + 2, nst);
        cpasync_commit();
        st = (st + 1 == NSTAGE) ? 0 : st + 1;
    }

    // epilogue
    #pragma unroll
    for (int j = 0; j < 4; j++) {
        const int col = col0 + lane + 32 * j;
        const float bj = bias[col];
        #pragma unroll
        for (int i = 0; i < 8; i++) {
            const int row = row0 + m0 + i;
            float v = d[i][j] + bj;
            if (GELU) v = 0.5f * v * (1.f + erff(v * 0.70710678118654752f));
            if (sizeof(OutT) == 4)
                *(float*)((float*)C + (size_t)row * N + col) = v;
            else
                *((__half*)C + (size_t)row * N + col) = __float2half(v);
        }
    }
    #undef ISSUE
}

// ---------------------------------------------------------------------------
// fp32 -> fp16 convert
// ---------------------------------------------------------------------------
__global__ __launch_bounds__(256)
void f2h_kernel(const float* __restrict__ in, __half* __restrict__ out, int n4)
{
    const int i = blockIdx.x * 256 + threadIdx.x;
    if (i < n4) {
        float4 v = ((const float4*)in)[i];
        ((__half2*)out)[2*i]   = __floats2half2_rn(v.x, v.y);
        ((__half2*)out)[2*i+1] = __floats2half2_rn(v.z, v.w);
    }
}

// ---------------------------------------------------------------------------
// Weight transpose + convert: out_h[n][k] = (half) in[k][n]
// ---------------------------------------------------------------------------
__global__ __launch_bounds__(256)
void transpose_h_kernel(const float* __restrict__ in, __half* __restrict__ out,
                        int R, int Ccols)   // in is [R][Ccols]
{
    __shared__ float tile[32][33];
    const int c = blockIdx.x * 32 + threadIdx.x;
    const int r = blockIdx.y * 32 + threadIdx.y;
    #pragma unroll
    for (int i = 0; i < 32; i += 8)
        tile[threadIdx.y + i][threadIdx.x] = in[(size_t)(r + i) * Ccols + c];
    __syncthreads();
    const int oc   = blockIdx.y * 32 + threadIdx.x;  // out col = orig row (K)
    const int orow = blockIdx.x * 32 + threadIdx.y;  // out row = orig col (N)
    #pragma unroll
    for (int i = 0; i < 32; i += 8)
        out[(size_t)(orow + i) * R + oc] = __float2half(tile[threadIdx.x][threadIdx.y + i]);
}

// ---------------------------------------------------------------------------
// Flash attention (causal), fp32 — unchanged from passing R6 kernel
// ---------------------------------------------------------------------------
#define ATT_P 68
#define ATT_SMEM (4 * 64 * ATT_P * 4)

__global__ __launch_bounds__(256)
void flash_attn_kernel(const float* __restrict__ qkv, float* __restrict__ y)
{
    extern __shared__ float smf[];
    float* Qs = smf;
    float* Ks = smf + 64*ATT_P;
    float* Vs = smf + 128*ATT_P;
    float* Ss = smf + 192*ATT_P;

    const int qt = blockIdx.x;
    const int bh = blockIdx.y;
    const int b  = bh >> 4;
    const int h  = bh & 15;
    const int t  = threadIdx.x;
    const int i  = t >> 2;
    const int cg = t & 3;
    const int c0 = cg << 4;
    const int qs = qt * 64;

    const size_t base = (size_t)(b * TSEQ) * C3 + h * HDIM;

    {
        const int d4 = (t & 15) * 4;
        const int r0 = t >> 4;
        #pragma unroll
        for (int rr = 0; rr < 64; rr += 16) {
            int row = r0 + rr;
            *(float4*)&Qs[row*ATT_P + d4] =
                *(const float4*)(qkv + base + (size_t)(qs + row) * C3 + d4);
        }
    }

    float m = -INFINITY, l = 0.f;
    float O[16];
    #pragma unroll
    for (int j = 0; j < 16; j++) O[j] = 0.f;

    for (int kt = 0; kt <= qt; kt++) {
        const int ks = kt * 64;
        __syncthreads();
        {
            const int d4 = (t & 15) * 4;
            const int r0 = t >> 4;
            #pragma unroll
            for (int rr = 0; rr < 64; rr += 16) {
                int row = r0 + rr;
                const float* kp = qkv + base + (size_t)(ks + row) * C3 + CEMB + d4;
                *(float4*)&Ks[row*ATT_P + d4] = *(const float4*)kp;
                *(float4*)&Vs[row*ATT_P + d4] = *(const float4*)(kp + CEMB);
            }
        }
        __syncthreads();

        float acc[16];
        #pragma unroll
        for (int jj = 0; jj < 16; jj++) acc[jj] = 0.f;
        #pragma unroll 4
        for (int d4 = 0; d4 < 64; d4 += 4) {
            float4 qv = *(const float4*)&Qs[i*ATT_P + d4];
            #pragma unroll
            for (int jj = 0; jj < 16; jj++) {
                float4 kv = *(const float4*)&Ks[(c0+jj)*ATT_P + d4];
                acc[jj] += qv.x*kv.x + qv.y*kv.y + qv.z*kv.z + qv.w*kv.w;
            }
        }

        const bool diag = (kt == qt);
        float mt = -INFINITY;
        #pragma unroll
        for (int jj = 0; jj < 16; jj++) {
            float s = acc[jj] * 0.125f;
            if (diag && (c0 + jj) > i) s = -INFINITY;
            acc[jj] = s;
            mt = fmaxf(mt, s);
        }
        mt = fmaxf(mt, __shfl_xor_sync(0xffffffffu, mt, 1));
        mt = fmaxf(mt, __shfl_xor_sync(0xffffffffu, mt, 2));
        const float mnew = fmaxf(m, mt);

        float lt = 0.f;
        #pragma unroll
        for (int jj = 0; jj < 16; jj++) {
            float p = __expf(acc[jj] - mnew);
            Ss[i*ATT_P + c0 + jj] = p;
            lt += p;
        }
        lt += __shfl_xor_sync(0xffffffffu, lt, 1);
        lt += __shfl_xor_sync(0xffffffffu, lt, 2);

        const float scale = __expf(m - mnew);
        m = mnew;
        l = l * scale + lt;
        #pragma unroll
        for (int cc = 0; cc < 16; cc++) O[cc] *= scale;
        __syncthreads();

        for (int j = 0; j < 64; j++) {
            float p = Ss[i*ATT_P + j];
            const float* vrow = &Vs[j*ATT_P + c0];
            #pragma unroll
            for (int cc4 = 0; cc4 < 16; cc4 += 4) {
                float4 vv = *(const float4*)(vrow + cc4);
                O[cc4+0] = fmaf(p, vv.x, O[cc4+0]);
                O[cc4+1] = fmaf(p, vv.y, O[cc4+1]);
                O[cc4+2] = fmaf(p, vv.z, O[cc4+2]);
                O[cc4+3] = fmaf(p, vv.w, O[cc4+3]);
            }
        }
    }

    const float inv = 1.f / l;
    float* dst = y + (size_t)(b * TSEQ + qs + i) * CEMB + h * HDIM + c0;
    #pragma unroll
    for (int cc = 0; cc < 16; cc++) dst[cc] = O[cc] * inv;
}

// ---------------------------------------------------------------------------
// Fused residual-add + LayerNorm; also writes half copy for next GEMM
// ---------------------------------------------------------------------------
__global__ __launch_bounds__(256)
void add_ln_kernel(const float* __restrict__ a, const float* __restrict__ r,
                   const float* __restrict__ gam, const float* __restrict__ bet,
                   float* __restrict__ out, __half* __restrict__ outh)
{
    const int row = blockIdx.x;
    const int t   = threadIdx.x;

    float4 va = ((const float4*)(a + (size_t)row * CEMB))[t];
    float4 vr = ((const float4*)(r + (size_t)row * CEMB))[t];
    float4 v;
    v.x = va.x + vr.x; v.y = va.y + vr.y; v.z = va.z + vr.z; v.w = va.w + vr.w;

    float s  = v.x + v.y + v.z + v.w;
    float sq = v.x*v.x + v.y*v.y + v.z*v.z + v.w*v.w;
    #pragma unroll
    for (int o = 16; o; o >>= 1) {
        s  += __shfl_xor_sync(0xffffffffu, s,  o);
        sq += __shfl_xor_sync(0xffffffffu, sq, o);
    }
    __shared__ float ps[8], pq[8];
    const int w = t >> 5, lane = t & 31;
    if (lane == 0) { ps[w] = s; pq[w] = sq; }
    __syncthreads();
    s = 0.f; sq = 0.f;
    #pragma unroll
    for (int k = 0; k < 8; k++) { s += ps[k]; sq += pq[k]; }

    const float mu   = s * (1.f / CEMB);
    const float var  = sq * (1.f / CEMB) - mu * mu;
    const float rstd = rsqrtf(var + LN_EPS);

    float4 gg = ((const float4*)gam)[t];
    float4 bb = ((const float4*)bet)[t];
    float4 o;
    o.x = (v.x - mu) * rstd * gg.x + bb.x;
    o.y = (v.y - mu) * rstd * gg.y + bb.y;
    o.z = (v.z - mu) * rstd * gg.z + bb.z;
    o.w = (v.w - mu) * rstd * gg.w + bb.w;
    ((float4*)(out + (size_t)row * CEMB))[t] = o;
    __half2* oh = (__half2*)(outh + (size_t)row * CEMB);
    oh[2*t]   = __floats2half2_rn(o.x, o.y);
    oh[2*t+1] = __floats2half2_rn(o.z, o.w);
}

// ---------------------------------------------------------------------------
// Launch
// ---------------------------------------------------------------------------
extern "C" void kernel_launch(void* const* d_in, const int* in_sizes, int n_in,
                              void* d_out, int out_size)
{
    const float* x     = (const float*)d_in[0];
    const float* w_qkv = (const float*)d_in[1];
    const float* b_qkv = (const float*)d_in[2];
    const float* ln1_g = (const float*)d_in[3];
    const float* ln1_b = (const float*)d_in[4];
    const float* w_fc1 = (const float*)d_in[5];
    const float* b_fc1 = (const float*)d_in[6];
    const float* w_fc2 = (const float*)d_in[7];
    const float* b_fc2 = (const float*)d_in[8];
    const float* ln2_g = (const float*)d_in[9];
    const float* ln2_b = (const float*)d_in[10];
    float* out = (float*)d_out;

    void *p_qkv, *p_att, *p_xn, *p_mlp, *p_xh, *p_xnh, *p_hh, *p_wq, *p_w1, *p_w2;
    cudaGetSymbolAddress(&p_qkv, g_qkv);
    cudaGetSymbolAddress(&p_att, g_att);
    cudaGetSymbolAddress(&p_xn,  g_xn);
    cudaGetSymbolAddress(&p_mlp, g_mlp);
    cudaGetSymbolAddress(&p_xh,  g_xh);
    cudaGetSymbolAddress(&p_xnh, g_xnh);
    cudaGetSymbolAddress(&p_hh,  g_hh);
    cudaGetSymbolAddress(&p_wq,  g_wTq);
    cudaGetSymbolAddress(&p_w1,  g_wT1);
    cudaGetSymbolAddress(&p_w2,  g_wT2);
    float*  qkv  = (float*)p_qkv;
    float*  att  = (float*)p_att;
    float*  xn   = (float*)p_xn;
    float*  mlp  = (float*)p_mlp;
    __half* xh   = (__half*)p_xh;
    __half* xnh  = (__half*)p_xnh;
    __half* hh   = (__half*)p_hh;
    __half* wTq  = (__half*)p_wq;
    __half* wT1  = (__half*)p_w1;
    __half* wT2  = (__half*)p_w2;

    cudaFuncSetAttribute(flash_attn_kernel,
                         cudaFuncAttributeMaxDynamicSharedMemorySize, ATT_SMEM);
    cudaFuncSetAttribute((const void*)h2gemm_kernel<false, float>,
                         cudaFuncAttributeMaxDynamicSharedMemorySize, GT_SMEM);
    cudaFuncSetAttribute((const void*)h2gemm_kernel<true, __half>,
                         cudaFuncAttributeMaxDynamicSharedMemorySize, GT_SMEM);

    // 0) conversions
    f2h_kernel<<<(NROWS*CEMB/4 + 255)/256, 256>>>(x, xh, NROWS*CEMB/4);
    transpose_h_kernel<<<dim3(C3/32,  CEMB/32), dim3(32,8)>>>(w_qkv, wTq, CEMB, C3);
    transpose_h_kernel<<<dim3(CFF/32, CEMB/32), dim3(32,8)>>>(w_fc1, wT1, CEMB, CFF);
    transpose_h_kernel<<<dim3(CEMB/32, CFF/32), dim3(32,8)>>>(w_fc2, wT2, CFF, CEMB);

    // 1) QKV projection (fp32 out)
    h2gemm_kernel<false, float><<<dim3(C3/128, NROWS/128), 512, GT_SMEM>>>(
        xh, wTq, b_qkv, qkv, NROWS, C3, CEMB);

    // 2) causal attention (fp32)
    flash_attn_kernel<<<dim3(TSEQ/64, BATCH*NHEAD), 256, ATT_SMEM>>>(qkv, att);

    // 3) xn = LN1(x + att) (+ half copy)
    add_ln_kernel<<<NROWS, 256>>>(x, att, ln1_g, ln1_b, xn, xnh);

    // 4) h = gelu(xn @ w_fc1 + b_fc1) (half out)
    h2gemm_kernel<true, __half><<<dim3(CFF/128, NROWS/128), 512, GT_SMEM>>>(
        xnh, wT1, b_fc1, hh, NROWS, CFF, CEMB);

    // 5) mlp = h @ w_fc2 + b_fc2 (fp32 out)
    h2gemm_kernel<false, float><<<dim3(CEMB/128, NROWS/128), 512, GT_SMEM>>>(
        hh, wT2, b_fc2, mlp, NROWS, CEMB, CFF);

    // 6) out = LN2(xn + mlp)  (half copy to dead buffer)
    add_ln_kernel<<<NROWS, 256>>>(xn, mlp, ln2_g, ln2_b, out, xnh);
}

// round 11
// speedup vs baseline: 1.6001x; 1.6001x over previous
#include <cuda_runtime.h>
#include <cuda_fp16.h>
#include <math.h>
#include <cstdint>

// ---------------------------------------------------------------------------
// Problem constants
// ---------------------------------------------------------------------------
#define BATCH   4
#define TSEQ    2048
#define CEMB    1024
#define NHEAD   16
#define HDIM    64
#define C3      (3*CEMB)      // 3072
#define CFF     (4*CEMB)      // 4096
#define NROWS   (BATCH*TSEQ)  // 8192
#define LN_EPS  1e-5f

// ---------------------------------------------------------------------------
// Scratch (__device__ globals; alloc-free rule)
// ---------------------------------------------------------------------------
__device__ float  g_qkv[(size_t)NROWS * C3];     // fp32 (attention input)
__device__ float  g_att[(size_t)NROWS * CEMB];
__device__ float  g_xn [(size_t)NROWS * CEMB];
__device__ float  g_mlp[(size_t)NROWS * CEMB];
__device__ __half g_xh [(size_t)NROWS * CEMB];   // x in half
__device__ __half g_xnh[(size_t)NROWS * CEMB];   // xn in half
__device__ __half g_hh [(size_t)NROWS * CFF];    // gelu(fc1) in half
__device__ __half g_wTq[(size_t)C3  * CEMB];     // [3072,1024] half (K-major)
__device__ __half g_wT1[(size_t)CFF * CEMB];
__device__ __half g_wT2[(size_t)CEMB * CFF];

// ---------------------------------------------------------------------------
// Helpers (family-portable)
// ---------------------------------------------------------------------------
__device__ __forceinline__ uint32_t smem_u32(const void* p) {
    uint32_t a;
    asm("{ .reg .u64 t; cvta.to.shared.u64 t, %1; cvt.u32.u64 %0, t; }"
        : "=r"(a) : "l"(p));
    return a;
}

// SW128 swizzle on byte offsets (rows are 128 bytes)
#define SWZ(o) ((o) ^ (((o) >> 3) & 0x70))

__device__ __forceinline__ void ldmx4(uint32_t* r, uint32_t addr) {
    asm volatile("ldmatrix.sync.aligned.m8n8.x4.shared.b16 {%0,%1,%2,%3}, [%4];"
                 : "=r"(r[0]), "=r"(r[1]), "=r"(r[2]), "=r"(r[3]) : "r"(addr));
}

__device__ __forceinline__ void mma16816(float* d, const uint32_t* a,
                                         const uint32_t* b) {
    asm volatile(
        "mma.sync.aligned.m16n8k16.row.col.f32.f16.f16.f32 "
        "{%0,%1,%2,%3}, {%4,%5,%6,%7}, {%8,%9}, {%0,%1,%2,%3};"
        : "+f"(d[0]), "+f"(d[1]), "+f"(d[2]), "+f"(d[3])
        : "r"(a[0]), "r"(a[1]), "r"(a[2]), "r"(a[3]), "r"(b[0]), "r"(b[1]));
}

__device__ __forceinline__ void cpasync16(uint32_t s, const void* g) {
    asm volatile("cp.async.cg.shared.global [%0], [%1], 16;" :: "r"(s), "l"(g));
}
__device__ __forceinline__ void cpasync_commit() {
    asm volatile("cp.async.commit_group;" ::: "memory");
}
template<int N>
__device__ __forceinline__ void cpasync_wait() {
    asm volatile("cp.async.wait_group %0;" :: "n"(N) : "memory");
}

// ---------------------------------------------------------------------------
// tcgen05 helpers (only referenced from the arch-specific branch; inline-only
// so no PTX is emitted for them in family passes)
// ---------------------------------------------------------------------------
__device__ __forceinline__ uint32_t elect1() {
    uint32_t p;
    asm volatile("{ .reg .pred p; elect.sync _|p, 0xFFFFFFFF; selp.b32 %0,1,0,p; }"
                 : "=r"(p));
    return p;
}
__device__ __forceinline__ void mbar_init(uint32_t mbar, uint32_t cnt) {
    asm volatile("mbarrier.init.shared.b64 [%0], %1;" :: "r"(mbar), "r"(cnt) : "memory");
}
__device__ __forceinline__ void mbar_wait(uint32_t mbar, uint32_t parity) {
    asm volatile(
        "{\n\t.reg .pred P;\n\t"
        "W%=:\n\t"
        "mbarrier.try_wait.parity.acquire.cta.shared::cta.b64 P, [%0], %1, 0x989680;\n\t"
        "@P bra.uni D%=;\n\t"
        "bra.uni W%=;\n\t"
        "D%=:\n\t}"
        :: "r"(mbar), "r"(parity) : "memory");
}
__device__ __forceinline__ void tc_alloc(uint32_t smem_dst, uint32_t ncols) {
    asm volatile("tcgen05.alloc.cta_group::1.sync.aligned.shared::cta.b32 [%0], %1;"
                 :: "r"(smem_dst), "r"(ncols) : "memory");
}
__device__ __forceinline__ void tc_relinq() {
    asm volatile("tcgen05.relinquish_alloc_permit.cta_group::1.sync.aligned;");
}
__device__ __forceinline__ void tc_dealloc(uint32_t tmem, uint32_t ncols) {
    asm volatile("tcgen05.dealloc.cta_group::1.sync.aligned.b32 %0, %1;"
                 :: "r"(tmem), "r"(ncols));
}
__device__ __forceinline__ void tc_commit(uint32_t mbar) {
    asm volatile("tcgen05.commit.cta_group::1.mbarrier::arrive::one.shared::cluster.b64 [%0];"
                 :: "r"(mbar) : "memory");
}
__device__ __forceinline__ void tc_fence_after() {
    asm volatile("tcgen05.fence::after_thread_sync;" ::: "memory");
}
__device__ __forceinline__ void tc_fence_before() {
    asm volatile("tcgen05.fence::before_thread_sync;" ::: "memory");
}
__device__ __forceinline__ void tc_wait_ld() {
    asm volatile("tcgen05.wait::ld.sync.aligned;" ::: "memory");
}
__device__ __forceinline__ void fence_proxy_async_sh() {
    asm volatile("fence.proxy.async.shared::cta;" ::: "memory");
}
// tcgen05 SS MMA, kind::f16 (fp16 x fp16 -> fp32 accum in TMEM)
__device__ __forceinline__ void mma_f16_ss(uint32_t d, uint64_t a, uint64_t b,
                                           uint32_t idesc, uint32_t en) {
    asm volatile(
        "{\n\t.reg .pred p;\n\t"
        "setp.ne.u32 p, %4, 0;\n\t"
        "tcgen05.mma.cta_group::1.kind::f16 [%0], %1, %2, %3, {%5,%5,%5,%5}, p;\n\t"
        "}"
        :: "r"(d), "l"(a), "l"(b), "r"(idesc), "r"(en), "r"(0u) : "memory");
}

#define TC_LD_X32(r, addr)                                                     \
    asm volatile(                                                              \
        "tcgen05.ld.sync.aligned.32x32b.x32.b32 "                              \
        "{%0, %1, %2, %3, %4, %5, %6, %7, "                                    \
        " %8, %9, %10, %11, %12, %13, %14, %15, "                              \
        " %16, %17, %18, %19, %20, %21, %22, %23, "                            \
        " %24, %25, %26, %27, %28, %29, %30, %31}, [%32];"                     \
        : "=r"((r)[0]),  "=r"((r)[1]),  "=r"((r)[2]),  "=r"((r)[3]),           \
          "=r"((r)[4]),  "=r"((r)[5]),  "=r"((r)[6]),  "=r"((r)[7]),           \
          "=r"((r)[8]),  "=r"((r)[9]),  "=r"((r)[10]), "=r"((r)[11]),          \
          "=r"((r)[12]), "=r"((r)[13]), "=r"((r)[14]), "=r"((r)[15]),          \
          "=r"((r)[16]), "=r"((r)[17]), "=r"((r)[18]), "=r"((r)[19]),          \
          "=r"((r)[20]), "=r"((r)[21]), "=r"((r)[22]), "=r"((r)[23]),          \
          "=r"((r)[24]), "=r"((r)[25]), "=r"((r)[26]), "=r"((r)[27]),          \
          "=r"((r)[28]), "=r"((r)[29]), "=r"((r)[30]), "=r"((r)[31])           \
        : "r"(addr))

// SW128 smem matrix descriptor (K-major, 128B rows): layout=SW128, ver=1,
// SBO=64 (1024B between 8-row swizzle blocks), LBO=1 (16B)
__device__ __forceinline__ uint64_t make_desc_sw128(uint32_t addr) {
    return (2ull << 61) | (1ull << 46) | (64ull << 32) | (1ull << 16)
         | ((uint64_t)(addr >> 4) & 0x3FFF);
}

// idesc kind::f16: dtype=F32(1<<4), atype=F16(0), btype=F16(0),
// N=128 ((128/8)<<17), M=128 ((128/16)<<24)
#define IDESC_F16_128x128 0x8200010u

// ---------------------------------------------------------------------------
// GEMM: C[M,N] = A[M,K]@Bt[N,K]^T + bias (opt GeLU). A,Bt half, C OutT.
// Arch-specific pass: tcgen05 kind::f16 SS MMA, fp32 TMEM accumulator.
// Family pass fallback: emulated mma.sync (R6 path, measured 6866us total).
// ---------------------------------------------------------------------------
#define BK 64
#define TILE_BYTES 16384       // 128 rows x 128 bytes
#define STAGE_BYTES 32768      // A tile + B tile
#define NSTAGE 3
#define GT_SMEM (NSTAGE * STAGE_BYTES)   // 98304

template<bool GELU, typename OutT>
__global__ __launch_bounds__(256, 2)
void hgemm_kernel(const __half* __restrict__ A, const __half* __restrict__ Bt,
                  const float* __restrict__ bias, OutT* __restrict__ C,
                  int M, int N, int K)
{
    extern __shared__ char sm[];
    const uint32_t sbase = smem_u32(sm);

    const int t    = threadIdx.x;
    const int wid  = t >> 5;
    const int lane = t & 31;
    const int row0 = blockIdx.y * 128;
    const int col0 = blockIdx.x * 128;
    const int KT   = K / BK;

    // per-thread staging coords (4 chunks per operand per stage)
    const int srow[4] = { (t + 0)   >> 3, (t + 256) >> 3,
                          (t + 512) >> 3, (t + 768) >> 3 };
    const int sch = t & 7;
    const uint32_t sso[4] = {
        SWZ((uint32_t)(srow[0] * 128 + sch * 16)),
        SWZ((uint32_t)(srow[1] * 128 + sch * 16)),
        SWZ((uint32_t)(srow[2] * 128 + sch * 16)),
        SWZ((uint32_t)(srow[3] * 128 + sch * 16)) };

#if defined(__CUDA_ARCH__) && defined(__CUDA_ARCH_SPECIFIC__)
    // =====================================================================
    // tcgen05 path (sm_103a arch-specific)
    // smem: [0]=tmem ptr, [8],[16]=mbarriers, stages at +1024 (2 x 32KB)
    // =====================================================================
    if (wid == 0) tc_alloc(sbase + 0, 128);
    if (t == 0) { mbar_init(sbase + 8, 1); mbar_init(sbase + 16, 1); }
    __syncthreads();
    uint32_t tmem;
    asm volatile("ld.shared.b32 %0, [%1];" : "=r"(tmem) : "r"(sbase + 0));
    if (wid == 0) tc_relinq();

    const uint32_t stb[2] = { sbase + 1024u, sbase + 1024u + 32768u };

    #define TISSUE(kt, st)                                                     \
        {                                                                      \
            const int kk_ = (kt) * BK;                                         \
            const uint32_t ab = stb[st];                                       \
            const uint32_t bb = ab + 16384u;                                   \
            _Pragma("unroll")                                                  \
            for (int it = 0; it < 4; it++) {                                   \
                cpasync16(ab + sso[it],                                        \
                          A  + (size_t)(row0 + srow[it]) * K + kk_ + sch * 8); \
                cpasync16(bb + sso[it],                                        \
                          Bt + (size_t)(col0 + srow[it]) * K + kk_ + sch * 8); \
            }                                                                  \
        }

    TISSUE(0, 0); cpasync_commit();

    for (int kt = 0; kt < KT; kt++) {
        const int buf = kt & 1;
        cpasync_wait<0>();       // stage kt fully resident
        __syncthreads();

        if (wid == 0) {
            if (elect1()) {
                fence_proxy_async_sh();
                const uint64_t ad = make_desc_sw128(stb[buf]);
                const uint64_t bd = make_desc_sw128(stb[buf] + 16384u);
                #pragma unroll
                for (int s = 0; s < 4; s++)       // 4 x K=16 per stage
                    mma_f16_ss(tmem, ad + 2 * s, bd + 2 * s,
                               IDESC_F16_128x128, (kt > 0 || s > 0) ? 1u : 0u);
                tc_commit(sbase + 8 + 8 * buf);
            }
        }

        // before restaging buf^1: MMAs of kt-1 (reading buf^1) must be done
        if (kt >= 1) mbar_wait(sbase + 8 + 8 * (buf ^ 1), ((kt - 1) >> 1) & 1);
        if (kt + 1 < KT) { TISSUE(kt + 1, buf ^ 1); }
        cpasync_commit();
    }

    // final MMA completion
    mbar_wait(sbase + 8 + 8 * ((KT - 1) & 1), ((KT - 1) >> 1) & 1);
    tc_fence_after();

    if (wid < 4) {
        const int row = row0 + wid * 32 + lane;
        #pragma unroll
        for (int ch = 0; ch < 4; ch++) {
            uint32_t r[32];
            TC_LD_X32(r, tmem + ch * 32);
            tc_wait_ld();
            const int colb = col0 + ch * 32;
            const float* bsrc = bias + colb;
            float vb[32];
            #pragma unroll
            for (int j = 0; j < 32; j++) {
                float v = __uint_as_float(r[j]) + bsrc[j];
                if (GELU) v = 0.5f * v * (1.f + erff(v * 0.70710678118654752f));
                vb[j] = v;
            }
            if (sizeof(OutT) == 4) {
                float* dst = (float*)C + (size_t)row * N + colb;
                #pragma unroll
                for (int j = 0; j < 32; j += 4)
                    *(float4*)(dst + j) = make_float4(vb[j], vb[j+1], vb[j+2], vb[j+3]);
            } else {
                __half2* dst = (__half2*)((__half*)C + (size_t)row * N + colb);
                #pragma unroll
                for (int j = 0; j < 16; j++)
                    dst[j] = __floats2half2_rn(vb[2*j], vb[2*j+1]);
            }
        }
        tc_fence_before();
    }
    __syncthreads();
    if (wid == 0) tc_dealloc(tmem, 128);
    #undef TISSUE
#else
    // =====================================================================
    // Fallback: emulated mma.sync path (R6, fma-pipe ceiling)
    // =====================================================================
    const int wm = wid & 1;        // 2 warp-rows of 64
    const int wn = wid >> 1;       // 4 warp-cols of 32

    #define ISSUE(kt, st)                                                      \
        {                                                                      \
            const int kk_ = (kt) * BK;                                         \
            const uint32_t ab = sbase + (uint32_t)(st) * STAGE_BYTES;          \
            const uint32_t bb = ab + TILE_BYTES;                               \
            _Pragma("unroll")                                                  \
            for (int it = 0; it < 4; it++) {                                   \
                cpasync16(ab + sso[it],                                        \
                          A  + (size_t)(row0 + srow[it]) * K + kk_ + sch * 8); \
                cpasync16(bb + sso[it],                                        \
                          Bt + (size_t)(col0 + srow[it]) * K + kk_ + sch * 8); \
            }                                                                  \
        }

    float d[4][4][4];
    #pragma unroll
    for (int mt = 0; mt < 4; mt++)
        #pragma unroll
        for (int nt = 0; nt < 4; nt++)
            #pragma unroll
            for (int rr = 0; rr < 4; rr++)
                d[mt][nt][rr] = 0.f;

    ISSUE(0, 0); cpasync_commit();
    ISSUE(1, 1); cpasync_commit();

    int st = 0;
    for (int kt = 0; kt < KT; kt++) {
        cpasync_wait<1>();
        __syncthreads();

        const uint32_t sa = sbase + (uint32_t)st * STAGE_BYTES;
        const uint32_t sb = sa + TILE_BYTES;

        #pragma unroll
        for (int kc = 0; kc < 4; kc++) {
            uint32_t afr[4][4];
            #pragma unroll
            for (int mt = 0; mt < 4; mt++) {
                const int arow = wm * 64 + mt * 16 + (lane & 15);
                const int ach  = kc * 2 + (lane >> 4);
                ldmx4(afr[mt], sa + SWZ((uint32_t)(arow * 128 + ach * 16)));
            }
            uint32_t bfr[2][4];
            #pragma unroll
            for (int nt2 = 0; nt2 < 2; nt2++) {
                const int brow = wn * 32 + nt2 * 16 + ((lane >> 4) << 3) + (lane & 7);
                const int bch  = kc * 2 + ((lane >> 3) & 1);
                ldmx4(bfr[nt2], sb + SWZ((uint32_t)(brow * 128 + bch * 16)));
            }
            #pragma unroll
            for (int mt = 0; mt < 4; mt++)
                #pragma unroll
                for (int nt = 0; nt < 4; nt++)
                    mma16816(d[mt][nt], afr[mt], &bfr[nt >> 1][(nt & 1) * 2]);
        }

        const int nst = (st + 2 >= NSTAGE) ? st + 2 - NSTAGE : st + 2;
        if (kt + 2 < KT) ISSUE(kt + 2, nst);
        cpasync_commit();
        st = (st + 1 == NSTAGE) ? 0 : st + 1;
    }

    const int er = lane >> 2;
    const int ec = (lane & 3) * 2;
    #pragma unroll
    for (int mt = 0; mt < 4; mt++) {
        #pragma unroll
        for (int nt = 0; nt < 4; nt++) {
            const int col = col0 + wn * 32 + nt * 8 + ec;
            const float b0 = bias[col], b1 = bias[col + 1];
            #pragma unroll
            for (int hf = 0; hf < 2; hf++) {
                const int row = row0 + wm * 64 + mt * 16 + er + hf * 8;
                float v0 = d[mt][nt][hf * 2 + 0] + b0;
                float v1 = d[mt][nt][hf * 2 + 1] + b1;
                if (GELU) {
                    v0 = 0.5f * v0 * (1.f + erff(v0 * 0.70710678118654752f));
                    v1 = 0.5f * v1 * (1.f + erff(v1 * 0.70710678118654752f));
                }
                OutT* dst = C + (size_t)row * N + col;
                if (sizeof(OutT) == 4) {
                    *(float2*)dst = make_float2(v0, v1);
                } else {
                    *(__half2*)dst = __floats2half2_rn(v0, v1);
                }
            }
        }
    }
    #undef ISSUE
#endif
}

// ---------------------------------------------------------------------------
// fp32 -> fp16 convert
// ---------------------------------------------------------------------------
__global__ __launch_bounds__(256)
void f2h_kernel(const float* __restrict__ in, __half* __restrict__ out, int n4)
{
    const int i = blockIdx.x * 256 + threadIdx.x;
    if (i < n4) {
        float4 v = ((const float4*)in)[i];
        ((__half2*)out)[2*i]   = __floats2half2_rn(v.x, v.y);
        ((__half2*)out)[2*i+1] = __floats2half2_rn(v.z, v.w);
    }
}

// ---------------------------------------------------------------------------
// Weight transpose + convert: out_h[n][k] = (half) in[k][n]
// ---------------------------------------------------------------------------
__global__ __launch_bounds__(256)
void transpose_h_kernel(const float* __restrict__ in, __half* __restrict__ out,
                        int R, int Ccols)   // in is [R][Ccols]
{
    __shared__ float tile[32][33];
    const int c = blockIdx.x * 32 + threadIdx.x;
    const int r = blockIdx.y * 32 + threadIdx.y;
    #pragma unroll
    for (int i = 0; i < 32; i += 8)
        tile[threadIdx.y + i][threadIdx.x] = in[(size_t)(r + i) * Ccols + c];
    __syncthreads();
    const int oc   = blockIdx.y * 32 + threadIdx.x;  // out col = orig row (K)
    const int orow = blockIdx.x * 32 + threadIdx.y;  // out row = orig col (N)
    #pragma unroll
    for (int i = 0; i < 32; i += 8)
        out[(size_t)(orow + i) * R + oc] = __float2half(tile[threadIdx.x][threadIdx.y + i]);
}

// ---------------------------------------------------------------------------
// Flash attention (causal), fp32
// ---------------------------------------------------------------------------
#define ATT_P 68
#define ATT_SMEM (4 * 64 * ATT_P * 4)

__global__ __launch_bounds__(256)
void flash_attn_kernel(const float* __restrict__ qkv, float* __restrict__ y)
{
    extern __shared__ float smf[];
    float* Qs = smf;
    float* Ks = smf + 64*ATT_P;
    float* Vs = smf + 128*ATT_P;
    float* Ss = smf + 192*ATT_P;

    const int qt = blockIdx.x;
    const int bh = blockIdx.y;
    const int b  = bh >> 4;
    const int h  = bh & 15;
    const int t  = threadIdx.x;
    const int i  = t >> 2;
    const int cg = t & 3;
    const int c0 = cg << 4;
    const int qs = qt * 64;

    const size_t base = (size_t)(b * TSEQ) * C3 + h * HDIM;

    {
        const int d4 = (t & 15) * 4;
        const int r0 = t >> 4;
        #pragma unroll
        for (int rr = 0; rr < 64; rr += 16) {
            int row = r0 + rr;
            *(float4*)&Qs[row*ATT_P + d4] =
                *(const float4*)(qkv + base + (size_t)(qs + row) * C3 + d4);
        }
    }

    float m = -INFINITY, l = 0.f;
    float O[16];
    #pragma unroll
    for (int j = 0; j < 16; j++) O[j] = 0.f;

    for (int kt = 0; kt <= qt; kt++) {
        const int ks = kt * 64;
        __syncthreads();
        {
            const int d4 = (t & 15) * 4;
            const int r0 = t >> 4;
            #pragma unroll
            for (int rr = 0; rr < 64; rr += 16) {
                int row = r0 + rr;
                const float* kp = qkv + base + (size_t)(ks + row) * C3 + CEMB + d4;
                *(float4*)&Ks[row*ATT_P + d4] = *(const float4*)kp;
                *(float4*)&Vs[row*ATT_P + d4] = *(const float4*)(kp + CEMB);
            }
        }
        __syncthreads();

        float acc[16];
        #pragma unroll
        for (int jj = 0; jj < 16; jj++) acc[jj] = 0.f;
        #pragma unroll 4
        for (int d4 = 0; d4 < 64; d4 += 4) {
            float4 qv = *(const float4*)&Qs[i*ATT_P + d4];
            #pragma unroll
            for (int jj = 0; jj < 16; jj++) {
                float4 kv = *(const float4*)&Ks[(c0+jj)*ATT_P + d4];
                acc[jj] += qv.x*kv.x + qv.y*kv.y + qv.z*kv.z + qv.w*kv.w;
            }
        }

        const bool diag = (kt == qt);
        float mt = -INFINITY;
        #pragma unroll
        for (int jj = 0; jj < 16; jj++) {
            float s = acc[jj] * 0.125f;
            if (diag && (c0 + jj) > i) s = -INFINITY;
            acc[jj] = s;
            mt = fmaxf(mt, s);
        }
        mt = fmaxf(mt, __shfl_xor_sync(0xffffffffu, mt, 1));
        mt = fmaxf(mt, __shfl_xor_sync(0xffffffffu, mt, 2));
        const float mnew = fmaxf(m, mt);

        float lt = 0.f;
        #pragma unroll
        for (int jj = 0; jj < 16; jj++) {
            float p = __expf(acc[jj] - mnew);
            Ss[i*ATT_P + c0 + jj] = p;
            lt += p;
        }
        lt += __shfl_xor_sync(0xffffffffu, lt, 1);
        lt += __shfl_xor_sync(0xffffffffu, lt, 2);

        const float scale = __expf(m - mnew);
        m = mnew;
        l = l * scale + lt;
        #pragma unroll
        for (int cc = 0; cc < 16; cc++) O[cc] *= scale;
        __syncthreads();

        for (int j = 0; j < 64; j++) {
            float p = Ss[i*ATT_P + j];
            const float* vrow = &Vs[j*ATT_P + c0];
            #pragma unroll
            for (int cc4 = 0; cc4 < 16; cc4 += 4) {
                float4 vv = *(const float4*)(vrow + cc4);
                O[cc4+0] = fmaf(p, vv.x, O[cc4+0]);
                O[cc4+1] = fmaf(p, vv.y, O[cc4+1]);
                O[cc4+2] = fmaf(p, vv.z, O[cc4+2]);
                O[cc4+3] = fmaf(p, vv.w, O[cc4+3]);
            }
        }
    }

    const float inv = 1.f / l;
    float* dst = y + (size_t)(b * TSEQ + qs + i) * CEMB + h * HDIM + c0;
    #pragma unroll
    for (int cc = 0; cc < 16; cc++) dst[cc] = O[cc] * inv;
}

// ---------------------------------------------------------------------------
// Fused residual-add + LayerNorm; also writes half copy for next GEMM
// ---------------------------------------------------------------------------
__global__ __launch_bounds__(256)
void add_ln_kernel(const float* __restrict__ a, const float* __restrict__ r,
                   const float* __restrict__ gam, const float* __restrict__ bet,
                   float* __restrict__ out, __half* __restrict__ outh)
{
    const int row = blockIdx.x;
    const int t   = threadIdx.x;

    float4 va = ((const float4*)(a + (size_t)row * CEMB))[t];
    float4 vr = ((const float4*)(r + (size_t)row * CEMB))[t];
    float4 v;
    v.x = va.x + vr.x; v.y = va.y + vr.y; v.z = va.z + vr.z; v.w = va.w + vr.w;

    float s  = v.x + v.y + v.z + v.w;
    float sq = v.x*v.x + v.y*v.y + v.z*v.z + v.w*v.w;
    #pragma unroll
    for (int o = 16; o; o >>= 1) {
        s  += __shfl_xor_sync(0xffffffffu, s,  o);
        sq += __shfl_xor_sync(0xffffffffu, sq, o);
    }
    __shared__ float ps[8], pq[8];
    const int w = t >> 5, lane = t & 31;
    if (lane == 0) { ps[w] = s; pq[w] = sq; }
    __syncthreads();
    s = 0.f; sq = 0.f;
    #pragma unroll
    for (int k = 0; k < 8; k++) { s += ps[k]; sq += pq[k]; }

    const float mu   = s * (1.f / CEMB);
    const float var  = sq * (1.f / CEMB) - mu * mu;
    const float rstd = rsqrtf(var + LN_EPS);

    float4 gg = ((const float4*)gam)[t];
    float4 bb = ((const float4*)bet)[t];
    float4 o;
    o.x = (v.x - mu) * rstd * gg.x + bb.x;
    o.y = (v.y - mu) * rstd * gg.y + bb.y;
    o.z = (v.z - mu) * rstd * gg.z + bb.z;
    o.w = (v.w - mu) * rstd * gg.w + bb.w;
    ((float4*)(out + (size_t)row * CEMB))[t] = o;
    __half2* oh = (__half2*)(outh + (size_t)row * CEMB);
    oh[2*t]   = __floats2half2_rn(o.x, o.y);
    oh[2*t+1] = __floats2half2_rn(o.z, o.w);
}

// ---------------------------------------------------------------------------
// Launch
// ---------------------------------------------------------------------------
extern "C" void kernel_launch(void* const* d_in, const int* in_sizes, int n_in,
                              void* d_out, int out_size)
{
    const float* x     = (const float*)d_in[0];
    const float* w_qkv = (const float*)d_in[1];
    const float* b_qkv = (const float*)d_in[2];
    const float* ln1_g = (const float*)d_in[3];
    const float* ln1_b = (const float*)d_in[4];
    const float* w_fc1 = (const float*)d_in[5];
    const float* b_fc1 = (const float*)d_in[6];
    const float* w_fc2 = (const float*)d_in[7];
    const float* b_fc2 = (const float*)d_in[8];
    const float* ln2_g = (const float*)d_in[9];
    const float* ln2_b = (const float*)d_in[10];
    float* out = (float*)d_out;

    void *p_qkv, *p_att, *p_xn, *p_mlp, *p_xh, *p_xnh, *p_hh, *p_wq, *p_w1, *p_w2;
    cudaGetSymbolAddress(&p_qkv, g_qkv);
    cudaGetSymbolAddress(&p_att, g_att);
    cudaGetSymbolAddress(&p_xn,  g_xn);
    cudaGetSymbolAddress(&p_mlp, g_mlp);
    cudaGetSymbolAddress(&p_xh,  g_xh);
    cudaGetSymbolAddress(&p_xnh, g_xnh);
    cudaGetSymbolAddress(&p_hh,  g_hh);
    cudaGetSymbolAddress(&p_wq,  g_wTq);
    cudaGetSymbolAddress(&p_w1,  g_wT1);
    cudaGetSymbolAddress(&p_w2,  g_wT2);
    float*  qkv  = (float*)p_qkv;
    float*  att  = (float*)p_att;
    float*  xn   = (float*)p_xn;
    float*  mlp  = (float*)p_mlp;
    __half* xh   = (__half*)p_xh;
    __half* xnh  = (__half*)p_xnh;
    __half* hh   = (__half*)p_hh;
    __half* wTq  = (__half*)p_wq;
    __half* wT1  = (__half*)p_w1;
    __half* wT2  = (__half*)p_w2;

    cudaFuncSetAttribute(flash_attn_kernel,
                         cudaFuncAttributeMaxDynamicSharedMemorySize, ATT_SMEM);
    cudaFuncSetAttribute((const void*)hgemm_kernel<false, float>,
                         cudaFuncAttributeMaxDynamicSharedMemorySize, GT_SMEM);
    cudaFuncSetAttribute((const void*)hgemm_kernel<true, __half>,
                         cudaFuncAttributeMaxDynamicSharedMemorySize, GT_SMEM);

    // 0) conversions
    f2h_kernel<<<(NROWS*CEMB/4 + 255)/256, 256>>>(x, xh, NROWS*CEMB/4);
    transpose_h_kernel<<<dim3(C3/32,  CEMB/32), dim3(32,8)>>>(w_qkv, wTq, CEMB, C3);
    transpose_h_kernel<<<dim3(CFF/32, CEMB/32), dim3(32,8)>>>(w_fc1, wT1, CEMB, CFF);
    transpose_h_kernel<<<dim3(CEMB/32, CFF/32), dim3(32,8)>>>(w_fc2, wT2, CFF, CEMB);

    // 1) QKV projection (fp32 out)
    hgemm_kernel<false, float><<<dim3(C3/128, NROWS/128), 256, GT_SMEM>>>(
        xh, wTq, b_qkv, qkv, NROWS, C3, CEMB);

    // 2) causal attention (fp32)
    flash_attn_kernel<<<dim3(TSEQ/64, BATCH*NHEAD), 256, ATT_SMEM>>>(qkv, att);

    // 3) xn = LN1(x + att) (+ half copy)
    add_ln_kernel<<<NROWS, 256>>>(x, att, ln1_g, ln1_b, xn, xnh);

    // 4) h = gelu(xn @ w_fc1 + b_fc1) (half out)
    hgemm_kernel<true, __half><<<dim3(CFF/128, NROWS/128), 256, GT_SMEM>>>(
        xnh, wT1, b_fc1, hh, NROWS, CFF, CEMB);

    // 5) mlp = h @ w_fc2 + b_fc2 (fp32 out)
    hgemm_kernel<false, float><<<dim3(CEMB/128, NROWS/128), 256, GT_SMEM>>>(
        hh, wT2, b_fc2, mlp, NROWS, CEMB, CFF);

    // 6) out = LN2(xn + mlp)  (half copy to dead buffer)
    add_ln_kernel<<<NROWS, 256>>>(xn, mlp, ln2_g, ln2_b, out, xnh);
}

// round 12
// speedup vs baseline: 1.6275x; 1.0171x over previous
#include <cuda_runtime.h>
#include <cuda_fp16.h>
#include <math.h>
#include <cstdint>

// ---------------------------------------------------------------------------
// Problem constants
// ---------------------------------------------------------------------------
#define BATCH   4
#define TSEQ    2048
#define CEMB    1024
#define NHEAD   16
#define HDIM    64
#define C3      (3*CEMB)      // 3072
#define CFF     (4*CEMB)      // 4096
#define NROWS   (BATCH*TSEQ)  // 8192
#define LN_EPS  1e-5f

// ---------------------------------------------------------------------------
// Scratch (__device__ globals; alloc-free rule)
// ---------------------------------------------------------------------------
__device__ float  g_qkv[(size_t)NROWS * C3];     // fp32 (attention input)
__device__ float  g_att[(size_t)NROWS * CEMB];
__device__ float  g_xn [(size_t)NROWS * CEMB];
__device__ float  g_mlp[(size_t)NROWS * CEMB];
__device__ __half g_xh [(size_t)NROWS * CEMB];   // x in half
__device__ __half g_xnh[(size_t)NROWS * CEMB];   // xn in half
__device__ __half g_hh [(size_t)NROWS * CFF];    // gelu(fc1) in half
__device__ __half g_wTq[(size_t)C3  * CEMB];     // [3072,1024] half (K-major)
__device__ __half g_wT1[(size_t)CFF * CEMB];
__device__ __half g_wT2[(size_t)CEMB * CFF];

// ---------------------------------------------------------------------------
// Helpers
// ---------------------------------------------------------------------------
__device__ __forceinline__ uint32_t smem_u32(const void* p) {
    uint32_t a;
    asm("{ .reg .u64 t; cvta.to.shared.u64 t, %1; cvt.u32.u64 %0, t; }"
        : "=r"(a) : "l"(p));
    return a;
}

// SW128 swizzle on byte offsets (rows are 128 bytes)
#define SWZ(o) ((o) ^ (((o) >> 3) & 0x70))

__device__ __forceinline__ void ldmx4(uint32_t* r, uint32_t addr) {
    asm volatile("ldmatrix.sync.aligned.m8n8.x4.shared.b16 {%0,%1,%2,%3}, [%4];"
                 : "=r"(r[0]), "=r"(r[1]), "=r"(r[2]), "=r"(r[3]) : "r"(addr));
}

__device__ __forceinline__ void mma16816(float* d, const uint32_t* a,
                                         const uint32_t* b) {
    asm volatile(
        "mma.sync.aligned.m16n8k16.row.col.f32.f16.f16.f32 "
        "{%0,%1,%2,%3}, {%4,%5,%6,%7}, {%8,%9}, {%0,%1,%2,%3};"
        : "+f"(d[0]), "+f"(d[1]), "+f"(d[2]), "+f"(d[3])
        : "r"(a[0]), "r"(a[1]), "r"(a[2]), "r"(a[3]), "r"(b[0]), "r"(b[1]));
}

__device__ __forceinline__ void cpasync16(uint32_t s, const void* g) {
    asm volatile("cp.async.cg.shared.global [%0], [%1], 16;" :: "r"(s), "l"(g));
}
__device__ __forceinline__ void cpasync_commit() {
    asm volatile("cp.async.commit_group;" ::: "memory");
}
template<int N>
__device__ __forceinline__ void cpasync_wait() {
    asm volatile("cp.async.wait_group %0;" :: "n"(N) : "memory");
}

// ---------------------------------------------------------------------------
// GEMM: C[M,N] = A[M,K]@Bt[N,K]^T + bias (opt GeLU). A,Bt half, C OutT.
// Emulated mma.sync at ~93% of chip fma-issue ceiling (R6 champion, frozen).
// CTA tile 128x128, BK=64 halfs (128B rows), 8 warps each 64x32.
// cp.async 3-stage pipeline (96KB smem), 2 CTAs/SM.
// ---------------------------------------------------------------------------
#define BK 64
#define TILE_BYTES 16384       // 128 rows x 128 bytes
#define STAGE_BYTES 32768      // A tile + B tile
#define NSTAGE 3
#define GT_SMEM (NSTAGE * STAGE_BYTES)   // 98304

template<bool GELU, typename OutT>
__global__ __launch_bounds__(256, 2)
void hgemm_kernel(const __half* __restrict__ A, const __half* __restrict__ Bt,
                  const float* __restrict__ bias, OutT* __restrict__ C,
                  int M, int N, int K)
{
    extern __shared__ char sm[];
    const uint32_t sbase = smem_u32(sm);

    const int t    = threadIdx.x;
    const int wid  = t >> 5;
    const int lane = t & 31;
    const int wm   = wid & 1;      // 2 warp-rows of 64
    const int wn   = wid >> 1;     // 4 warp-cols of 32
    const int row0 = blockIdx.y * 128;
    const int col0 = blockIdx.x * 128;

    const int KT = K / BK;

    const int srow[4] = { (t + 0)   >> 3, (t + 256) >> 3,
                          (t + 512) >> 3, (t + 768) >> 3 };
    const int sch = t & 7;
    const uint32_t sso[4] = {
        SWZ((uint32_t)(srow[0] * 128 + sch * 16)),
        SWZ((uint32_t)(srow[1] * 128 + sch * 16)),
        SWZ((uint32_t)(srow[2] * 128 + sch * 16)),
        SWZ((uint32_t)(srow[3] * 128 + sch * 16)) };

    #define ISSUE(kt, st)                                                      \
        {                                                                      \
            const int kk_ = (kt) * BK;                                         \
            const uint32_t ab = sbase + (uint32_t)(st) * STAGE_BYTES;          \
            const uint32_t bb = ab + TILE_BYTES;                               \
            _Pragma("unroll")                                                  \
            for (int it = 0; it < 4; it++) {                                   \
                cpasync16(ab + sso[it],                                        \
                          A  + (size_t)(row0 + srow[it]) * K + kk_ + sch * 8); \
                cpasync16(bb + sso[it],                                        \
                          Bt + (size_t)(col0 + srow[it]) * K + kk_ + sch * 8); \
            }                                                                  \
        }

    float d[4][4][4];
    #pragma unroll
    for (int mt = 0; mt < 4; mt++)
        #pragma unroll
        for (int nt = 0; nt < 4; nt++)
            #pragma unroll
            for (int rr = 0; rr < 4; rr++)
                d[mt][nt][rr] = 0.f;

    ISSUE(0, 0); cpasync_commit();
    ISSUE(1, 1); cpasync_commit();

    int st = 0;
    for (int kt = 0; kt < KT; kt++) {
        cpasync_wait<1>();
        __syncthreads();

        const uint32_t sa = sbase + (uint32_t)st * STAGE_BYTES;
        const uint32_t sb = sa + TILE_BYTES;

        #pragma unroll
        for (int kc = 0; kc < 4; kc++) {
            uint32_t afr[4][4];
            #pragma unroll
            for (int mt = 0; mt < 4; mt++) {
                const int arow = wm * 64 + mt * 16 + (lane & 15);
                const int ach  = kc * 2 + (lane >> 4);
                ldmx4(afr[mt], sa + SWZ((uint32_t)(arow * 128 + ach * 16)));
            }
            uint32_t bfr[2][4];
            #pragma unroll
            for (int nt2 = 0; nt2 < 2; nt2++) {
                const int brow = wn * 32 + nt2 * 16 + ((lane >> 4) << 3) + (lane & 7);
                const int bch  = kc * 2 + ((lane >> 3) & 1);
                ldmx4(bfr[nt2], sb + SWZ((uint32_t)(brow * 128 + bch * 16)));
            }
            #pragma unroll
            for (int mt = 0; mt < 4; mt++)
                #pragma unroll
                for (int nt = 0; nt < 4; nt++)
                    mma16816(d[mt][nt], afr[mt], &bfr[nt >> 1][(nt & 1) * 2]);
        }

        const int nst = (st + 2 >= NSTAGE) ? st + 2 - NSTAGE : st + 2;
        if (kt + 2 < KT) ISSUE(kt + 2, nst);
        cpasync_commit();
        st = (st + 1 == NSTAGE) ? 0 : st + 1;
    }

    const int er = lane >> 2;
    const int ec = (lane & 3) * 2;
    #pragma unroll
    for (int mt = 0; mt < 4; mt++) {
        #pragma unroll
        for (int nt = 0; nt < 4; nt++) {
            const int col = col0 + wn * 32 + nt * 8 + ec;
            const float b0 = bias[col], b1 = bias[col + 1];
            #pragma unroll
            for (int hf = 0; hf < 2; hf++) {
                const int row = row0 + wm * 64 + mt * 16 + er + hf * 8;
                float v0 = d[mt][nt][hf * 2 + 0] + b0;
                float v1 = d[mt][nt][hf * 2 + 1] + b1;
                if (GELU) {
                    v0 = 0.5f * v0 * (1.f + erff(v0 * 0.70710678118654752f));
                    v1 = 0.5f * v1 * (1.f + erff(v1 * 0.70710678118654752f));
                }
                OutT* dst = C + (size_t)row * N + col;
                if (sizeof(OutT) == 4) {
                    *(float2*)dst = make_float2(v0, v1);
                } else {
                    *(__half2*)dst = __floats2half2_rn(v0, v1);
                }
            }
        }
    }
    #undef ISSUE
}

// ---------------------------------------------------------------------------
// fp32 -> fp16 convert
// ---------------------------------------------------------------------------
__global__ __launch_bounds__(256)
void f2h_kernel(const float* __restrict__ in, __half* __restrict__ out, int n4)
{
    const int i = blockIdx.x * 256 + threadIdx.x;
    if (i < n4) {
        float4 v = ((const float4*)in)[i];
        ((__half2*)out)[2*i]   = __floats2half2_rn(v.x, v.y);
        ((__half2*)out)[2*i+1] = __floats2half2_rn(v.z, v.w);
    }
}

// ---------------------------------------------------------------------------
// Weight transpose + convert: out_h[n][k] = (half) in[k][n]
// ---------------------------------------------------------------------------
__global__ __launch_bounds__(256)
void transpose_h_kernel(const float* __restrict__ in, __half* __restrict__ out,
                        int R, int Ccols)   // in is [R][Ccols]
{
    __shared__ float tile[32][33];
    const int c = blockIdx.x * 32 + threadIdx.x;
    const int r = blockIdx.y * 32 + threadIdx.y;
    #pragma unroll
    for (int i = 0; i < 32; i += 8)
        tile[threadIdx.y + i][threadIdx.x] = in[(size_t)(r + i) * Ccols + c];
    __syncthreads();
    const int oc   = blockIdx.y * 32 + threadIdx.x;  // out col = orig row (K)
    const int orow = blockIdx.x * 32 + threadIdx.y;  // out row = orig col (N)
    #pragma unroll
    for (int i = 0; i < 32; i += 8)
        out[(size_t)(orow + i) * R + oc] = __float2half(tile[threadIdx.x][threadIdx.y + i]);
}

// ---------------------------------------------------------------------------
// Flash attention (causal), fp32. cp.async double-buffered K/V pipeline:
// tile kt+1 streams in while tile kt computes. One __syncthreads per tile;
// the P (Ss) tile is same-warp-private so PV needs only __syncwarp.
// smem: Qs | K0 | V0 | K1 | V1 | Ss  (6 x 17408B = 102KB, 2 CTAs/SM)
// ---------------------------------------------------------------------------
#define ATT_P 68
#define ATT_TILE (64 * ATT_P * 4)          // 17408
#define ATT_SMEM (6 * ATT_TILE)            // 104448

__global__ __launch_bounds__(256, 2)
void flash_attn_kernel(const float* __restrict__ qkv, float* __restrict__ y)
{
    extern __shared__ float smf[];
    float* Qs  = smf;
    float* Kb[2] = { smf + 64*ATT_P,  smf + 192*ATT_P };
    float* Vb[2] = { smf + 128*ATT_P, smf + 256*ATT_P };
    float* Ss  = smf + 320*ATT_P;
    const uint32_t sb = smem_u32(smf);

    const int qt = blockIdx.x;
    const int bh = blockIdx.y;
    const int b  = bh >> 4;
    const int h  = bh & 15;
    const int t  = threadIdx.x;
    const int i  = t >> 2;
    const int cg = t & 3;
    const int c0 = cg << 4;
    const int qs = qt * 64;

    const size_t base = (size_t)(b * TSEQ) * C3 + h * HDIM;

    // staging coords for K/V cp.async: 16 chunks (16B) per row, 16 rows/pass
    const int sd4 = (t & 15) * 4;         // float offset within row
    const int sr  = t >> 4;               // row 0..15 (+16 steps)

    // preload K/V tile 0 + Q tile (Q via regular loads, once)
    {
        const uint32_t kdst = sb + (uint32_t)(64*ATT_P*4);   // Kb[0]
        const uint32_t vdst = sb + (uint32_t)(128*ATT_P*4);  // Vb[0]
        #pragma unroll
        for (int rr = 0; rr < 64; rr += 16) {
            const int row = sr + rr;
            const float* kp = qkv + base + (size_t)row * C3 + CEMB + sd4;
            cpasync16(kdst + (uint32_t)((row*ATT_P + sd4)*4), kp);
            cpasync16(vdst + (uint32_t)((row*ATT_P + sd4)*4), kp + CEMB);
        }
        cpasync_commit();
        #pragma unroll
        for (int rr = 0; rr < 64; rr += 16) {
            const int row = sr + rr;
            *(float4*)&Qs[row*ATT_P + sd4] =
                *(const float4*)(qkv + base + (size_t)(qs + row) * C3 + sd4);
        }
    }

    float m = -INFINITY, l = 0.f;
    float O[16];
    #pragma unroll
    for (int j = 0; j < 16; j++) O[j] = 0.f;

    for (int kt = 0; kt <= qt; kt++) {
        cpasync_wait<0>();       // tile kt resident
        __syncthreads();         // all warps done with buffer kt^1 compute

        // stream tile kt+1 into the other buffer (overlaps compute below)
        if (kt < qt) {
            const int nb = (kt + 1) & 1;
            const int ks1 = (kt + 1) * 64;
            const uint32_t kdst = sb + (uint32_t)((64 + 128*nb)*ATT_P*4);
            const uint32_t vdst = kdst + (uint32_t)(64*ATT_P*4);
            #pragma unroll
            for (int rr = 0; rr < 64; rr += 16) {
                const int row = sr + rr;
                const float* kp = qkv + base + (size_t)(ks1 + row) * C3 + CEMB + sd4;
                cpasync16(kdst + (uint32_t)((row*ATT_P + sd4)*4), kp);
                cpasync16(vdst + (uint32_t)((row*ATT_P + sd4)*4), kp + CEMB);
            }
        }
        cpasync_commit();

        const float* Ks = Kb[kt & 1];
        const float* Vs = Vb[kt & 1];

        float acc[16];
        #pragma unroll
        for (int jj = 0; jj < 16; jj++) acc[jj] = 0.f;
        #pragma unroll 4
        for (int d4 = 0; d4 < 64; d4 += 4) {
            float4 qv = *(const float4*)&Qs[i*ATT_P + d4];
            #pragma unroll
            for (int jj = 0; jj < 16; jj++) {
                float4 kv = *(const float4*)&Ks[(c0+jj)*ATT_P + d4];
                acc[jj] += qv.x*kv.x + qv.y*kv.y + qv.z*kv.z + qv.w*kv.w;
            }
        }

        const bool diag = (kt == qt);
        float mt = -INFINITY;
        #pragma unroll
        for (int jj = 0; jj < 16; jj++) {
            float s = acc[jj] * 0.125f;
            if (diag && (c0 + jj) > i) s = -INFINITY;
            acc[jj] = s;
            mt = fmaxf(mt, s);
        }
        mt = fmaxf(mt, __shfl_xor_sync(0xffffffffu, mt, 1));
        mt = fmaxf(mt, __shfl_xor_sync(0xffffffffu, mt, 2));
        const float mnew = fmaxf(m, mt);

        float lt = 0.f;
        #pragma unroll
        for (int jj = 0; jj < 16; jj++) {
            float p = __expf(acc[jj] - mnew);
            Ss[i*ATT_P + c0 + jj] = p;
            lt += p;
        }
        lt += __shfl_xor_sync(0xffffffffu, lt, 1);
        lt += __shfl_xor_sync(0xffffffffu, lt, 2);

        const float scale = __expf(m - mnew);
        m = mnew;
        l = l * scale + lt;
        #pragma unroll
        for (int cc = 0; cc < 16; cc++) O[cc] *= scale;
        __syncwarp();            // Ss row i written by this warp only

        for (int j = 0; j < 64; j++) {
            float p = Ss[i*ATT_P + j];
            const float* vrow = &Vs[j*ATT_P + c0];
            #pragma unroll
            for (int cc4 = 0; cc4 < 16; cc4 += 4) {
                float4 vv = *(const float4*)(vrow + cc4);
                O[cc4+0] = fmaf(p, vv.x, O[cc4+0]);
                O[cc4+1] = fmaf(p, vv.y, O[cc4+1]);
                O[cc4+2] = fmaf(p, vv.z, O[cc4+2]);
                O[cc4+3] = fmaf(p, vv.w, O[cc4+3]);
            }
        }
    }

    const float inv = 1.f / l;
    float* dst = y + (size_t)(b * TSEQ + qs + i) * CEMB + h * HDIM + c0;
    #pragma unroll
    for (int cc = 0; cc < 16; cc++) dst[cc] = O[cc] * inv;
}

// ---------------------------------------------------------------------------
// Fused residual-add + LayerNorm; optional half emit for next GEMM
// ---------------------------------------------------------------------------
template<bool WRITEH>
__global__ __launch_bounds__(256)
void add_ln_kernel(const float* __restrict__ a, const float* __restrict__ r,
                   const float* __restrict__ gam, const float* __restrict__ bet,
                   float* __restrict__ out, __half* __restrict__ outh)
{
    const int row = blockIdx.x;
    const int t   = threadIdx.x;

    float4 va = ((const float4*)(a + (size_t)row * CEMB))[t];
    float4 vr = ((const float4*)(r + (size_t)row * CEMB))[t];
    float4 v;
    v.x = va.x + vr.x; v.y = va.y + vr.y; v.z = va.z + vr.z; v.w = va.w + vr.w;

    float s  = v.x + v.y + v.z + v.w;
    float sq = v.x*v.x + v.y*v.y + v.z*v.z + v.w*v.w;
    #pragma unroll
    for (int o = 16; o; o >>= 1) {
        s  += __shfl_xor_sync(0xffffffffu, s,  o);
        sq += __shfl_xor_sync(0xffffffffu, sq, o);
    }
    __shared__ float ps[8], pq[8];
    const int w = t >> 5, lane = t & 31;
    if (lane == 0) { ps[w] = s; pq[w] = sq; }
    __syncthreads();
    s = 0.f; sq = 0.f;
    #pragma unroll
    for (int k = 0; k < 8; k++) { s += ps[k]; sq += pq[k]; }

    const float mu   = s * (1.f / CEMB);
    const float var  = sq * (1.f / CEMB) - mu * mu;
    const float rstd = rsqrtf(var + LN_EPS);

    float4 gg = ((const float4*)gam)[t];
    float4 bb = ((const float4*)bet)[t];
    float4 o;
    o.x = (v.x - mu) * rstd * gg.x + bb.x;
    o.y = (v.y - mu) * rstd * gg.y + bb.y;
    o.z = (v.z - mu) * rstd * gg.z + bb.z;
    o.w = (v.w - mu) * rstd * gg.w + bb.w;
    ((float4*)(out + (size_t)row * CEMB))[t] = o;
    if (WRITEH) {
        __half2* oh = (__half2*)(outh + (size_t)row * CEMB);
        oh[2*t]   = __floats2half2_rn(o.x, o.y);
        oh[2*t+1] = __floats2half2_rn(o.z, o.w);
    }
}

// ---------------------------------------------------------------------------
// Launch
// ---------------------------------------------------------------------------
extern "C" void kernel_launch(void* const* d_in, const int* in_sizes, int n_in,
                              void* d_out, int out_size)
{
    const float* x     = (const float*)d_in[0];
    const float* w_qkv = (const float*)d_in[1];
    const float* b_qkv = (const float*)d_in[2];
    const float* ln1_g = (const float*)d_in[3];
    const float* ln1_b = (const float*)d_in[4];
    const float* w_fc1 = (const float*)d_in[5];
    const float* b_fc1 = (const float*)d_in[6];
    const float* w_fc2 = (const float*)d_in[7];
    const float* b_fc2 = (const float*)d_in[8];
    const float* ln2_g = (const float*)d_in[9];
    const float* ln2_b = (const float*)d_in[10];
    float* out = (float*)d_out;

    void *p_qkv, *p_att, *p_xn, *p_mlp, *p_xh, *p_xnh, *p_hh, *p_wq, *p_w1, *p_w2;
    cudaGetSymbolAddress(&p_qkv, g_qkv);
    cudaGetSymbolAddress(&p_att, g_att);
    cudaGetSymbolAddress(&p_xn,  g_xn);
    cudaGetSymbolAddress(&p_mlp, g_mlp);
    cudaGetSymbolAddress(&p_xh,  g_xh);
    cudaGetSymbolAddress(&p_xnh, g_xnh);
    cudaGetSymbolAddress(&p_hh,  g_hh);
    cudaGetSymbolAddress(&p_wq,  g_wTq);
    cudaGetSymbolAddress(&p_w1,  g_wT1);
    cudaGetSymbolAddress(&p_w2,  g_wT2);
    float*  qkv  = (float*)p_qkv;
    float*  att  = (float*)p_att;
    float*  xn   = (float*)p_xn;
    float*  mlp  = (float*)p_mlp;
    __half* xh   = (__half*)p_xh;
    __half* xnh  = (__half*)p_xnh;
    __half* hh   = (__half*)p_hh;
    __half* wTq  = (__half*)p_wq;
    __half* wT1  = (__half*)p_w1;
    __half* wT2  = (__half*)p_w2;

    cudaFuncSetAttribute(flash_attn_kernel,
                         cudaFuncAttributeMaxDynamicSharedMemorySize, ATT_SMEM);
    cudaFuncSetAttribute((const void*)hgemm_kernel<false, float>,
                         cudaFuncAttributeMaxDynamicSharedMemorySize, GT_SMEM);
    cudaFuncSetAttribute((const void*)hgemm_kernel<true, __half>,
                         cudaFuncAttributeMaxDynamicSharedMemorySize, GT_SMEM);

    // 0) conversions
    f2h_kernel<<<(NROWS*CEMB/4 + 255)/256, 256>>>(x, xh, NROWS*CEMB/4);
    transpose_h_kernel<<<dim3(C3/32,  CEMB/32), dim3(32,8)>>>(w_qkv, wTq, CEMB, C3);
    transpose_h_kernel<<<dim3(CFF/32, CEMB/32), dim3(32,8)>>>(w_fc1, wT1, CEMB, CFF);
    transpose_h_kernel<<<dim3(CEMB/32, CFF/32), dim3(32,8)>>>(w_fc2, wT2, CFF, CEMB);

    // 1) QKV projection (fp32 out)
    hgemm_kernel<false, float><<<dim3(C3/128, NROWS/128), 256, GT_SMEM>>>(
        xh, wTq, b_qkv, qkv, NROWS, C3, CEMB);

    // 2) causal attention (fp32, pipelined K/V)
    flash_attn_kernel<<<dim3(TSEQ/64, BATCH*NHEAD), 256, ATT_SMEM>>>(qkv, att);

    // 3) xn = LN1(x + att) (+ half copy)
    add_ln_kernel<true><<<NROWS, 256>>>(x, att, ln1_g, ln1_b, xn, xnh);

    // 4) h = gelu(xn @ w_fc1 + b_fc1) (half out)
    hgemm_kernel<true, __half><<<dim3(CFF/128, NROWS/128), 256, GT_SMEM>>>(
        xnh, wT1, b_fc1, hh, NROWS, CFF, CEMB);

    // 5) mlp = h @ w_fc2 + b_fc2 (fp32 out)
    hgemm_kernel<false, float><<<dim3(CEMB/128, NROWS/128), 256, GT_SMEM>>>(
        hh, wT2, b_fc2, mlp, NROWS, CEMB, CFF);

    // 6) out = LN2(xn + mlp)
    add_ln_kernel<false><<<NROWS, 256>>>(xn, mlp, ln2_g, ln2_b, out, xnh);
}